// round 13
// baseline (speedup 1.0000x reference)
#include <cuda_runtime.h>
#include <cuda_bf16.h>
#include <cstdint>

#define C 32
#define NMAX 500000
#define LRELU 0.01f
#define BN_EPS 1e-5f

// Scratch (static device globals — allocation rules forbid cudaMalloc)
__device__ float g_conv[NMAX * C];        // 64 MB conv accumulator
__device__ uint4 g_split[NMAX * 8];       // 64 MB: per row [hi bf16 x32 | lo bf16 x32]
__device__ float g_stats[2 * C];          // [0:32) sum(act), [32:64) sum(act^2)

__device__ __forceinline__ uint32_t smem_u32(const void* p) {
    uint32_t a;
    asm("{ .reg .u64 t; cvta.to.shared.u64 t, %1; cvt.u32.u64 %0, t; }"
        : "=r"(a) : "l"(p));
    return a;
}
__device__ __forceinline__ void ldm4(uint32_t a[4], uint32_t addr) {
    asm volatile("ldmatrix.sync.aligned.m8n8.x4.shared.b16 {%0,%1,%2,%3}, [%4];"
                 : "=r"(a[0]), "=r"(a[1]), "=r"(a[2]), "=r"(a[3]) : "r"(addr));
}
__device__ __forceinline__ void mma_bf16(float d[4], const uint32_t a[4],
                                         uint32_t b0, uint32_t b1) {
    asm volatile("mma.sync.aligned.m16n8k16.row.col.f32.bf16.bf16.f32 "
                 "{%0,%1,%2,%3}, {%4,%5,%6,%7}, {%8,%9}, {%0,%1,%2,%3};"
                 : "+f"(d[0]), "+f"(d[1]), "+f"(d[2]), "+f"(d[3])
                 : "r"(a[0]), "r"(a[1]), "r"(a[2]), "r"(a[3]),
                   "r"(b0), "r"(b1));
}
__device__ __forceinline__ uint32_t bf2_u32(__nv_bfloat162 v) {
    return *reinterpret_cast<uint32_t*>(&v);
}
// pack hi16(x0), hi16(x1) -> bf16x2 (truncation split)
__device__ __forceinline__ uint32_t hi_pack(uint32_t x0, uint32_t x1) {
    uint32_t r;
    asm("prmt.b32 %0, %1, %2, 0x7632;" : "=r"(r) : "r"(x0), "r"(x1));
    return r;
}
// pack bf16(a), bf16(b) -> bf16x2 with lo-half = a
__device__ __forceinline__ uint32_t lo_pack(float a, float b) {
    uint32_t r;
    asm("cvt.rn.satfinite.bf16x2.f32 %0, %1, %2;" : "=r"(r) : "f"(b), "f"(a));
    return r;
}

// Fused: bf16 hi/lo split of features into g_split + zero g_conv + zero g_stats
__global__ void prep_kernel(const float* __restrict__ features, int N) {
    const int stride = gridDim.x * blockDim.x;
    const int tid0 = blockIdx.x * blockDim.x + threadIdx.x;
    // split: one thread handles 8 consecutive floats (one quarter row)
    const int total_q = N * 4;
    for (int i = tid0; i < total_q; i += stride) {
        const int r = i >> 2, q = i & 3;
        const float4 v0 = *((const float4*)(features + (size_t)r * C) + q * 2);
        const float4 v1 = *((const float4*)(features + (size_t)r * C) + q * 2 + 1);
        const uint32_t x0 = __float_as_uint(v0.x), x1 = __float_as_uint(v0.y);
        const uint32_t x2 = __float_as_uint(v0.z), x3 = __float_as_uint(v0.w);
        const uint32_t x4 = __float_as_uint(v1.x), x5 = __float_as_uint(v1.y);
        const uint32_t x6 = __float_as_uint(v1.z), x7 = __float_as_uint(v1.w);
        uint4 hi, lo;
        hi.x = hi_pack(x0, x1); hi.y = hi_pack(x2, x3);
        hi.z = hi_pack(x4, x5); hi.w = hi_pack(x6, x7);
        lo.x = lo_pack(v0.x - __uint_as_float(x0 & 0xFFFF0000u),
                       v0.y - __uint_as_float(x1 & 0xFFFF0000u));
        lo.y = lo_pack(v0.z - __uint_as_float(x2 & 0xFFFF0000u),
                       v0.w - __uint_as_float(x3 & 0xFFFF0000u));
        lo.z = lo_pack(v1.x - __uint_as_float(x4 & 0xFFFF0000u),
                       v1.y - __uint_as_float(x5 & 0xFFFF0000u));
        lo.w = lo_pack(v1.z - __uint_as_float(x6 & 0xFFFF0000u),
                       v1.w - __uint_as_float(x7 & 0xFFFF0000u));
        g_split[(size_t)r * 8 + q]     = hi;
        g_split[(size_t)r * 8 + 4 + q] = lo;
    }
    // zero conv accumulator
    float4 z = make_float4(0.f, 0.f, 0.f, 0.f);
    float4* p = reinterpret_cast<float4*>(g_conv);
    const int n_f4 = N * 8;
    for (int i = tid0; i < n_f4; i += stride) p[i] = z;
    if (tid0 < 2 * C) g_stats[tid0] = 0.f;
}

// Per-warp smem region (5120 B): bf16 A_hi[32][40] (2560 B) + A_lo[32][40];
// after the MMAs the same region is reused as float stage[32][40].
__global__ __launch_bounds__(256, 3) void conv_mma_kernel(
    const float* __restrict__ weight,
    const int* __restrict__ pairs_in,
    const int* __restrict__ pairs_out,
    int P, int tiles_per_k, int n_tiles, int chunk_sz)
{
    __shared__ float Ws[C * C];
    __shared__ uint32_t Bs[2][32][18];   // [hi/lo][lane][2f+half], padded stride
    __shared__ __align__(1024) unsigned char Asm[8][5120];

    const int wid  = threadIdx.x >> 5;
    const int lane = threadIdx.x & 31;
    const int sub   = lane >> 3;   // row-within-group 0..3
    const int chunk = lane & 7;    // 16B chunk 0..7

    unsigned char* Ab = &Asm[wid][0];
    const uint32_t Aw = smem_u32(Ab);
    float* stg = reinterpret_cast<float*>(Ab);

    const int t0 = blockIdx.x * chunk_sz;
    const int t1 = min(t0 + chunk_sz, n_tiles);
    int kprev = -1;

    for (int t = t0; t < t1; t++) {
        const int k     = t / tiles_per_k;
        const int tbase = (t - k * tiles_per_k) * 256;

        if (k != kprev) {
            kprev = k;
            __syncthreads();   // all warps done with previous Bs
            for (int i = threadIdx.x; i < C * C; i += 256)
                Ws[i] = weight[(size_t)k * (C * C) + i];
            __syncthreads();
            if (threadIdx.x < 32) {
                const int kq = (lane & 3) * 2, n = lane >> 2;
                #pragma unroll
                for (int kt = 0; kt < 2; kt++) {
                    #pragma unroll
                    for (int nt = 0; nt < 4; nt++) {
                        const int f = kt * 4 + nt;
                        const int k0 = kt * 16 + kq, nn = nt * 8 + n;
                        float w0 = Ws[k0 * C + nn];
                        float w1 = Ws[(k0 + 1) * C + nn];
                        float w2 = Ws[(k0 + 8) * C + nn];
                        float w3 = Ws[(k0 + 9) * C + nn];
                        __nv_bfloat16 h0 = __float2bfloat16_rn(w0);
                        __nv_bfloat16 h1 = __float2bfloat16_rn(w1);
                        __nv_bfloat16 h2 = __float2bfloat16_rn(w2);
                        __nv_bfloat16 h3 = __float2bfloat16_rn(w3);
                        Bs[0][lane][2 * f]     = bf2_u32(__halves2bfloat162(h0, h1));
                        Bs[0][lane][2 * f + 1] = bf2_u32(__halves2bfloat162(h2, h3));
                        Bs[1][lane][2 * f]     = lo_pack(w0 - __bfloat162float(h0),
                                                         w1 - __bfloat162float(h1));
                        Bs[1][lane][2 * f + 1] = lo_pack(w2 - __bfloat162float(h2),
                                                         w3 - __bfloat162float(h3));
                    }
                }
            }
            __syncthreads();
        }

        const int wbase = tbase + wid * 32;
        if (wbase >= P) continue;   // no barriers below -> safe divergence

        const int p = wbase + lane;
        const int pc = p < P ? p : P - 1;
        const int* __restrict__ pin  = pairs_in  + (size_t)k * P;
        const int* __restrict__ pout = pairs_out + (size_t)k * P;
        const int pi = pin[pc];
        const int po = pout[pc];

        // ---- coalesced gather of pre-split rows: pure LDG.128 -> STS.128 ----
        __syncwarp();
        #pragma unroll
        for (int it = 0; it < 8; it++) {
            const int slot = it * 4 + sub;
            const int row = __shfl_sync(0xffffffffu, pi, slot);
            const uint4 v = g_split[(size_t)row * 8 + chunk];
            *(uint4*)(Ab + (chunk < 4 ? 0 : 2560) + slot * 80 + (chunk & 3) * 16) = v;
        }
        __syncwarp();

        // ---- tensor-core compute: 48 HMMA (3 products x 2 m x 4 n x 2 k) ----
        float D[2][4][4] = {};
        const int r  = lane & 15;
        const int cb = (lane >> 4) * 16;
        #pragma unroll
        for (int mt = 0; mt < 2; mt++) {
            uint32_t Ah[2][4], Al[2][4];
            #pragma unroll
            for (int kt = 0; kt < 2; kt++) {
                const uint32_t ad = Aw + (mt * 16 + r) * 80 + cb + kt * 32;
                ldm4(Ah[kt], ad);
                ldm4(Al[kt], ad + 2560);
            }
            #pragma unroll
            for (int nt = 0; nt < 4; nt++) {
                #pragma unroll
                for (int kt = 0; kt < 2; kt++) {
                    const int f = kt * 4 + nt;
                    const uint2 bh = *(const uint2*)&Bs[0][lane][2 * f];
                    const uint2 bl = *(const uint2*)&Bs[1][lane][2 * f];
                    mma_bf16(D[mt][nt], Ah[kt], bh.x, bh.y);
                    mma_bf16(D[mt][nt], Ah[kt], bl.x, bl.y);
                    mma_bf16(D[mt][nt], Al[kt], bh.x, bh.y);
                }
            }
        }
        __syncwarp();   // all lanes done reading A tiles

        // ---- stage D fragments (stride-40 f32 rows) ----
        {
            const int drow = lane >> 2, dcol = (lane & 3) * 2;
            #pragma unroll
            for (int mt = 0; mt < 2; mt++) {
                #pragma unroll
                for (int nt = 0; nt < 4; nt++) {
                    *(float2*)&stg[(mt * 16 + drow) * 40 + nt * 8 + dcol] =
                        make_float2(D[mt][nt][0], D[mt][nt][1]);
                    *(float2*)&stg[(mt * 16 + drow + 8) * 40 + nt * 8 + dcol] =
                        make_float2(D[mt][nt][2], D[mt][nt][3]);
                }
            }
        }
        __syncwarp();

        // ---- cooperative coalesced scatter ----
        #pragma unroll
        for (int it = 0; it < 8; it++) {
            const int slot = it * 4 + sub;
            const int row = __shfl_sync(0xffffffffu, po, slot);
            if (wbase + slot < P) {
                const float4 v = *(const float4*)&stg[slot * 40 + chunk * 4];
                asm volatile("red.global.add.v4.f32 [%0], {%1, %2, %3, %4};"
                             :: "l"(g_conv + (size_t)row * C + chunk * 4),
                                "f"(v.x), "f"(v.y), "f"(v.z), "f"(v.w)
                             : "memory");
            }
        }
    }
}

__global__ void stats_kernel(int N) {
    __shared__ float4 ssum[256];
    __shared__ float4 sqsum[256];
    const int cg = threadIdx.x & 7;    // 16B chunk = channels cg*4..cg*4+3
    const int rr = threadIdx.x >> 3;   // row within block group (0..31)
    float4 s = make_float4(0.f, 0.f, 0.f, 0.f);
    float4 q = make_float4(0.f, 0.f, 0.f, 0.f);
    for (int row = blockIdx.x * 32 + rr; row < N; row += gridDim.x * 32) {
        const float4 v = *(const float4*)(g_conv + (size_t)row * C + cg * 4);
        const float a0 = v.x >= 0.f ? v.x : LRELU * v.x;
        const float a1 = v.y >= 0.f ? v.y : LRELU * v.y;
        const float a2 = v.z >= 0.f ? v.z : LRELU * v.z;
        const float a3 = v.w >= 0.f ? v.w : LRELU * v.w;
        s.x += a0; s.y += a1; s.z += a2; s.w += a3;
        q.x += a0 * a0; q.y += a1 * a1; q.z += a2 * a2; q.w += a3 * a3;
    }
    ssum[threadIdx.x] = s;
    sqsum[threadIdx.x] = q;
    __syncthreads();
    for (int st = 128; st >= 8; st >>= 1) {
        if (threadIdx.x < st) {
            float4 o = ssum[threadIdx.x + st];
            float4 oq = sqsum[threadIdx.x + st];
            float4 a = ssum[threadIdx.x];
            float4 aq = sqsum[threadIdx.x];
            a.x += o.x; a.y += o.y; a.z += o.z; a.w += o.w;
            aq.x += oq.x; aq.y += oq.y; aq.z += oq.z; aq.w += oq.w;
            ssum[threadIdx.x] = a;
            sqsum[threadIdx.x] = aq;
        }
        __syncthreads();
    }
    if (threadIdx.x < 8) {
        const float4 a = ssum[threadIdx.x];
        const float4 aq = sqsum[threadIdx.x];
        atomicAdd(&g_stats[threadIdx.x * 4 + 0], a.x);
        atomicAdd(&g_stats[threadIdx.x * 4 + 1], a.y);
        atomicAdd(&g_stats[threadIdx.x * 4 + 2], a.z);
        atomicAdd(&g_stats[threadIdx.x * 4 + 3], a.w);
        atomicAdd(&g_stats[C + threadIdx.x * 4 + 0], aq.x);
        atomicAdd(&g_stats[C + threadIdx.x * 4 + 1], aq.y);
        atomicAdd(&g_stats[C + threadIdx.x * 4 + 2], aq.z);
        atomicAdd(&g_stats[C + threadIdx.x * 4 + 3], aq.w);
    }
}

__global__ void final_kernel(const float* __restrict__ gamma,
                             const float* __restrict__ beta,
                             float* __restrict__ out, int N) {
    const int idx0 = blockIdx.x * blockDim.x + threadIdx.x;
    const int stride = gridDim.x * blockDim.x;   // multiple of 8 -> cg invariant
    const int cg = idx0 & 7;
    const float invN = 1.f / (float)N;
    float sc[4], sh[4];
    #pragma unroll
    for (int j = 0; j < 4; j++) {
        const int c = cg * 4 + j;
        const float mean = g_stats[c] * invN;
        const float var  = g_stats[C + c] * invN - mean * mean;
        sc[j] = rsqrtf(var + BN_EPS) * gamma[c];
        sh[j] = beta[c] - mean * sc[j];
    }
    const float4* __restrict__ cp = reinterpret_cast<const float4*>(g_conv);
    float4* __restrict__ op = reinterpret_cast<float4*>(out);
    const int total4 = N * 8;
    for (int idx = idx0; idx < total4; idx += stride) {
        const float4 v = cp[idx];
        float4 y;
        y.x = (v.x >= 0.f ? v.x : LRELU * v.x) * sc[0] + sh[0];
        y.y = (v.y >= 0.f ? v.y : LRELU * v.y) * sc[1] + sh[1];
        y.z = (v.z >= 0.f ? v.z : LRELU * v.z) * sc[2] + sh[2];
        y.w = (v.w >= 0.f ? v.w : LRELU * v.w) * sc[3] + sh[3];
        op[idx] = y;
    }
}

extern "C" void kernel_launch(void* const* d_in, const int* in_sizes, int n_in,
                              void* d_out, int out_size) {
    const float* features = (const float*)d_in[0];
    const float* weight   = (const float*)d_in[1];
    const float* gamma    = (const float*)d_in[2];
    const float* beta     = (const float*)d_in[3];
    const int*   pairs_in = (const int*)d_in[4];
    const int*   pairs_out= (const int*)d_in[5];
    float* out = (float*)d_out;

    const int N = in_sizes[0] / C;
    const int K = in_sizes[1] / (C * C);
    const int P = in_sizes[4] / K;

    prep_kernel<<<2048, 256>>>(features, N);

    const int tiles_per_k = (P + 255) / 256;
    const int n_tiles = K * tiles_per_k;
    const int nblocks = 444;   // 148 SMs x 3 CTAs
    const int chunk_sz = (n_tiles + nblocks - 1) / nblocks;
    conv_mma_kernel<<<nblocks, 256>>>(weight, pairs_in, pairs_out,
                                      P, tiles_per_k, n_tiles, chunk_sz);

    stats_kernel<<<1024, 256>>>(N);

    final_kernel<<<2048, 256>>>(gamma, beta, out, N);
}

// round 15
// speedup vs baseline: 1.1940x; 1.1940x over previous
#include <cuda_runtime.h>
#include <cuda_fp16.h>
#include <cstdint>

#define C 32
#define NMAX 500000
#define LRELU 0.01f
#define BN_EPS 1e-5f

// Scratch (static device globals — allocation rules forbid cudaMalloc)
__device__ float g_conv[NMAX * C];        // 64 MB conv accumulator
__device__ uint4 g_feat16[NMAX * 4];      // 32 MB: features as fp16, 64B per row
__device__ float g_stats[2 * C];          // [0:32) sum(act), [32:64) sum(act^2)

__device__ __forceinline__ uint32_t smem_u32(const void* p) {
    uint32_t a;
    asm("{ .reg .u64 t; cvta.to.shared.u64 t, %1; cvt.u32.u64 %0, t; }"
        : "=r"(a) : "l"(p));
    return a;
}
__device__ __forceinline__ void ldm4(uint32_t a[4], uint32_t addr) {
    asm volatile("ldmatrix.sync.aligned.m8n8.x4.shared.b16 {%0,%1,%2,%3}, [%4];"
                 : "=r"(a[0]), "=r"(a[1]), "=r"(a[2]), "=r"(a[3]) : "r"(addr));
}
__device__ __forceinline__ void mma_f16(float d[4], const uint32_t a[4],
                                        uint32_t b0, uint32_t b1) {
    asm volatile("mma.sync.aligned.m16n8k16.row.col.f32.f16.f16.f32 "
                 "{%0,%1,%2,%3}, {%4,%5,%6,%7}, {%8,%9}, {%0,%1,%2,%3};"
                 : "+f"(d[0]), "+f"(d[1]), "+f"(d[2]), "+f"(d[3])
                 : "r"(a[0]), "r"(a[1]), "r"(a[2]), "r"(a[3]),
                   "r"(b0), "r"(b1));
}
__device__ __forceinline__ uint32_t h2_u32(__half2 v) {
    return *reinterpret_cast<uint32_t*>(&v);
}

// Fused: fp16 pack of features into g_feat16 + zero g_conv + zero g_stats
__global__ void prep_kernel(const float* __restrict__ features, int N) {
    const int stride = gridDim.x * blockDim.x;
    const int tid0 = blockIdx.x * blockDim.x + threadIdx.x;
    const int total_q = N * 4;       // one 16B fp16 chunk (8 channels) per i
    for (int i = tid0; i < total_q; i += stride) {
        const float4 v0 = *((const float4*)features + (size_t)i * 2);
        const float4 v1 = *((const float4*)features + (size_t)i * 2 + 1);
        uint4 o;
        o.x = h2_u32(__float22half2_rn(make_float2(v0.x, v0.y)));
        o.y = h2_u32(__float22half2_rn(make_float2(v0.z, v0.w)));
        o.z = h2_u32(__float22half2_rn(make_float2(v1.x, v1.y)));
        o.w = h2_u32(__float22half2_rn(make_float2(v1.z, v1.w)));
        g_feat16[i] = o;
    }
    float4 z = make_float4(0.f, 0.f, 0.f, 0.f);
    float4* p = reinterpret_cast<float4*>(g_conv);
    const int n_f4 = N * 8;
    for (int i = tid0; i < n_f4; i += stride) p[i] = z;
    if (tid0 < 2 * C) g_stats[tid0] = 0.f;
}

// Per-warp smem region (5120 B): fp16 A[32][80B] in first 2560 B;
// after the MMAs the same region is reused as float stage[32][40].
__global__ __launch_bounds__(256, 3) void conv_mma_kernel(
    const float* __restrict__ weight,
    const int* __restrict__ pairs_in,
    const int* __restrict__ pairs_out,
    int P)
{
    __shared__ float Ws[C * C];
    __shared__ uint32_t Bs[2][32][18];   // [h0/h1][lane][2f+half], padded stride
    __shared__ __align__(1024) unsigned char Asm[8][5120];

    const int k = blockIdx.y;
    for (int i = threadIdx.x; i < C * C; i += blockDim.x)
        Ws[i] = weight[(size_t)k * (C * C) + i];
    __syncthreads();

    const int wid  = threadIdx.x >> 5;
    const int lane = threadIdx.x & 31;
    const int sub   = lane >> 3;   // scatter: row-within-group 0..3
    const int chunk = lane & 7;    // scatter: 16B chunk 0..7 (fp32 rows)
    const int sub8   = lane >> 2;  // gather: row-within-group 0..7
    const int chunk4 = lane & 3;   // gather: 16B chunk 0..3 (fp16 rows)

    // ---- B fragments: exact 2-way fp16 split of W[k] -> block-shared smem ----
    if (threadIdx.x < 32) {
        const int kq = (lane & 3) * 2, n = lane >> 2;
        #pragma unroll
        for (int kt = 0; kt < 2; kt++) {
            #pragma unroll
            for (int nt = 0; nt < 4; nt++) {
                const int f = kt * 4 + nt;
                const int k0 = kt * 16 + kq, nn = nt * 8 + n;
                const float w0 = Ws[k0 * C + nn];
                const float w1 = Ws[(k0 + 1) * C + nn];
                const float w2 = Ws[(k0 + 8) * C + nn];
                const float w3 = Ws[(k0 + 9) * C + nn];
                const __half a0 = __float2half_rn(w0);
                const __half a1 = __float2half_rn(w1);
                const __half a2 = __float2half_rn(w2);
                const __half a3 = __float2half_rn(w3);
                Bs[0][lane][2 * f]     = h2_u32(__halves2half2(a0, a1));
                Bs[0][lane][2 * f + 1] = h2_u32(__halves2half2(a2, a3));
                Bs[1][lane][2 * f]     = h2_u32(__halves2half2(
                    __float2half_rn(w0 - __half2float(a0)),
                    __float2half_rn(w1 - __half2float(a1))));
                Bs[1][lane][2 * f + 1] = h2_u32(__halves2half2(
                    __float2half_rn(w2 - __half2float(a2)),
                    __float2half_rn(w3 - __half2float(a3))));
            }
        }
    }
    __syncthreads();

    unsigned char* Ab = &Asm[wid][0];
    const uint32_t Aw = smem_u32(Ab);
    float* stg = reinterpret_cast<float*>(Ab);

    const int* __restrict__ pin  = pairs_in  + (size_t)k * P;
    const int* __restrict__ pout = pairs_out + (size_t)k * P;
    const int warp_global = blockIdx.x * 8 + wid;
    const int nwarps = gridDim.x * 8;

    for (int base = warp_global * 32; base < P; base += nwarps * 32) {
        const int p = base + lane;
        const int pc = p < P ? p : P - 1;
        const int pi = pin[pc];
        const int po = pout[pc];

        // ---- coalesced gather of fp16 rows: 4x (8 rows x 4 chunks) ----
        __syncwarp();
        #pragma unroll
        for (int it = 0; it < 4; it++) {
            const int slot = it * 8 + sub8;
            const int row = __shfl_sync(0xffffffffu, pi, slot);
            const uint4 v = g_feat16[(size_t)row * 4 + chunk4];
            *(uint4*)(Ab + slot * 80 + chunk4 * 16) = v;
        }
        __syncwarp();

        // ---- tensor-core compute: 32 HMMA (2 products x 2 m x 4 n x 2 k) ----
        float D[2][4][4] = {};
        const int r  = lane & 15;
        const int cb = (lane >> 4) * 16;
        #pragma unroll
        for (int mt = 0; mt < 2; mt++) {
            uint32_t A[2][4];
            #pragma unroll
            for (int kt = 0; kt < 2; kt++)
                ldm4(A[kt], Aw + (mt * 16 + r) * 80 + cb + kt * 32);
            #pragma unroll
            for (int nt = 0; nt < 4; nt++) {
                #pragma unroll
                for (int kt = 0; kt < 2; kt++) {
                    const int f = kt * 4 + nt;
                    const uint2 b0 = *(const uint2*)&Bs[0][lane][2 * f];
                    const uint2 b1 = *(const uint2*)&Bs[1][lane][2 * f];
                    mma_f16(D[mt][nt], A[kt], b0.x, b0.y);
                    mma_f16(D[mt][nt], A[kt], b1.x, b1.y);
                }
            }
        }
        __syncwarp();   // all lanes done reading A tile

        // ---- stage D fragments (stride-40 f32 rows) ----
        {
            const int drow = lane >> 2, dcol = (lane & 3) * 2;
            #pragma unroll
            for (int mt = 0; mt < 2; mt++) {
                #pragma unroll
                for (int nt = 0; nt < 4; nt++) {
                    *(float2*)&stg[(mt * 16 + drow) * 40 + nt * 8 + dcol] =
                        make_float2(D[mt][nt][0], D[mt][nt][1]);
                    *(float2*)&stg[(mt * 16 + drow + 8) * 40 + nt * 8 + dcol] =
                        make_float2(D[mt][nt][2], D[mt][nt][3]);
                }
            }
        }
        __syncwarp();

        // ---- cooperative coalesced scatter ----
        #pragma unroll
        for (int it = 0; it < 8; it++) {
            const int slot = it * 4 + sub;
            const int row = __shfl_sync(0xffffffffu, po, slot);
            if (base + slot < P) {
                const float4 v = *(const float4*)&stg[slot * 40 + chunk * 4];
                asm volatile("red.global.add.v4.f32 [%0], {%1, %2, %3, %4};"
                             :: "l"(g_conv + (size_t)row * C + chunk * 4),
                                "f"(v.x), "f"(v.y), "f"(v.z), "f"(v.w)
                             : "memory");
            }
        }
    }
}

__global__ void stats_kernel(int N) {
    __shared__ float4 ssum[256];
    __shared__ float4 sqsum[256];
    const int cg = threadIdx.x & 7;
    const int rr = threadIdx.x >> 3;
    float4 s = make_float4(0.f, 0.f, 0.f, 0.f);
    float4 q = make_float4(0.f, 0.f, 0.f, 0.f);
    for (int row = blockIdx.x * 32 + rr; row < N; row += gridDim.x * 32) {
        const float4 v = *(const float4*)(g_conv + (size_t)row * C + cg * 4);
        const float a0 = v.x >= 0.f ? v.x : LRELU * v.x;
        const float a1 = v.y >= 0.f ? v.y : LRELU * v.y;
        const float a2 = v.z >= 0.f ? v.z : LRELU * v.z;
        const float a3 = v.w >= 0.f ? v.w : LRELU * v.w;
        s.x += a0; s.y += a1; s.z += a2; s.w += a3;
        q.x += a0 * a0; q.y += a1 * a1; q.z += a2 * a2; q.w += a3 * a3;
    }
    ssum[threadIdx.x] = s;
    sqsum[threadIdx.x] = q;
    __syncthreads();
    for (int st = 128; st >= 8; st >>= 1) {
        if (threadIdx.x < st) {
            float4 o = ssum[threadIdx.x + st];
            float4 oq = sqsum[threadIdx.x + st];
            float4 a = ssum[threadIdx.x];
            float4 aq = sqsum[threadIdx.x];
            a.x += o.x; a.y += o.y; a.z += o.z; a.w += o.w;
            aq.x += oq.x; aq.y += oq.y; aq.z += oq.z; aq.w += oq.w;
            ssum[threadIdx.x] = a;
            sqsum[threadIdx.x] = aq;
        }
        __syncthreads();
    }
    if (threadIdx.x < 8) {
        const float4 a = ssum[threadIdx.x];
        const float4 aq = sqsum[threadIdx.x];
        atomicAdd(&g_stats[threadIdx.x * 4 + 0], a.x);
        atomicAdd(&g_stats[threadIdx.x * 4 + 1], a.y);
        atomicAdd(&g_stats[threadIdx.x * 4 + 2], a.z);
        atomicAdd(&g_stats[threadIdx.x * 4 + 3], a.w);
        atomicAdd(&g_stats[C + threadIdx.x * 4 + 0], aq.x);
        atomicAdd(&g_stats[C + threadIdx.x * 4 + 1], aq.y);
        atomicAdd(&g_stats[C + threadIdx.x * 4 + 2], aq.z);
        atomicAdd(&g_stats[C + threadIdx.x * 4 + 3], aq.w);
    }
}

__global__ void final_kernel(const float* __restrict__ gamma,
                             const float* __restrict__ beta,
                             float* __restrict__ out, int N) {
    const int idx0 = blockIdx.x * blockDim.x + threadIdx.x;
    const int stride = gridDim.x * blockDim.x;   // multiple of 8 -> cg invariant
    const int cg = idx0 & 7;
    const float invN = 1.f / (float)N;
    float sc[4], sh[4];
    #pragma unroll
    for (int j = 0; j < 4; j++) {
        const int c = cg * 4 + j;
        const float mean = g_stats[c] * invN;
        const float var  = g_stats[C + c] * invN - mean * mean;
        sc[j] = rsqrtf(var + BN_EPS) * gamma[c];
        sh[j] = beta[c] - mean * sc[j];
    }
    const float4* __restrict__ cp = reinterpret_cast<const float4*>(g_conv);
    float4* __restrict__ op = reinterpret_cast<float4*>(out);
    const int total4 = N * 8;
    for (int idx = idx0; idx < total4; idx += stride) {
        const float4 v = cp[idx];
        float4 y;
        y.x = (v.x >= 0.f ? v.x : LRELU * v.x) * sc[0] + sh[0];
        y.y = (v.y >= 0.f ? v.y : LRELU * v.y) * sc[1] + sh[1];
        y.z = (v.z >= 0.f ? v.z : LRELU * v.z) * sc[2] + sh[2];
        y.w = (v.w >= 0.f ? v.w : LRELU * v.w) * sc[3] + sh[3];
        op[idx] = y;
    }
}

extern "C" void kernel_launch(void* const* d_in, const int* in_sizes, int n_in,
                              void* d_out, int out_size) {
    const float* features = (const float*)d_in[0];
    const float* weight   = (const float*)d_in[1];
    const float* gamma    = (const float*)d_in[2];
    const float* beta     = (const float*)d_in[3];
    const int*   pairs_in = (const int*)d_in[4];
    const int*   pairs_out= (const int*)d_in[5];
    float* out = (float*)d_out;

    const int N = in_sizes[0] / C;
    const int K = in_sizes[1] / (C * C);
    const int P = in_sizes[4] / K;

    prep_kernel<<<2048, 256>>>(features, N);

    dim3 cgrid(64, K);
    conv_mma_kernel<<<cgrid, 256>>>(weight, pairs_in, pairs_out, P);

    stats_kernel<<<1024, 256>>>(N);

    final_kernel<<<2048, 256>>>(gamma, beta, out, N);
}

// round 16
// speedup vs baseline: 1.2066x; 1.0105x over previous
#include <cuda_runtime.h>
#include <cuda_fp16.h>
#include <cstdint>

#define C 32
#define NMAX 500000
#define LRELU 0.01f
#define BN_EPS 1e-5f

// Scratch (static device globals — allocation rules forbid cudaMalloc)
__device__ float g_conv[NMAX * C];        // 64 MB conv accumulator
__device__ uint4 g_feat16[NMAX * 4];      // 32 MB: features as fp16, 64B per row
__device__ float g_stats[2 * C];          // [0:32) sum(act), [32:64) sum(act^2)

__device__ __forceinline__ uint32_t smem_u32(const void* p) {
    uint32_t a;
    asm("{ .reg .u64 t; cvta.to.shared.u64 t, %1; cvt.u32.u64 %0, t; }"
        : "=r"(a) : "l"(p));
    return a;
}
__device__ __forceinline__ void ldm4(uint32_t a[4], uint32_t addr) {
    asm volatile("ldmatrix.sync.aligned.m8n8.x4.shared.b16 {%0,%1,%2,%3}, [%4];"
                 : "=r"(a[0]), "=r"(a[1]), "=r"(a[2]), "=r"(a[3]) : "r"(addr));
}
__device__ __forceinline__ void mma_f16(float d[4], const uint32_t a[4],
                                        uint32_t b0, uint32_t b1) {
    asm volatile("mma.sync.aligned.m16n8k16.row.col.f32.f16.f16.f32 "
                 "{%0,%1,%2,%3}, {%4,%5,%6,%7}, {%8,%9}, {%0,%1,%2,%3};"
                 : "+f"(d[0]), "+f"(d[1]), "+f"(d[2]), "+f"(d[3])
                 : "r"(a[0]), "r"(a[1]), "r"(a[2]), "r"(a[3]),
                   "r"(b0), "r"(b1));
}
__device__ __forceinline__ uint32_t h2_u32(__half2 v) {
    return *reinterpret_cast<uint32_t*>(&v);
}

// Fused: fp16 pack of features into g_feat16 + zero g_conv + zero g_stats
__global__ void prep_kernel(const float* __restrict__ features, int N) {
    const int stride = gridDim.x * blockDim.x;
    const int tid0 = blockIdx.x * blockDim.x + threadIdx.x;
    const int total_q = N * 4;       // one 16B fp16 chunk (8 channels) per i
    for (int i = tid0; i < total_q; i += stride) {
        const float4 v0 = *((const float4*)features + (size_t)i * 2);
        const float4 v1 = *((const float4*)features + (size_t)i * 2 + 1);
        uint4 o;
        o.x = h2_u32(__float22half2_rn(make_float2(v0.x, v0.y)));
        o.y = h2_u32(__float22half2_rn(make_float2(v0.z, v0.w)));
        o.z = h2_u32(__float22half2_rn(make_float2(v1.x, v1.y)));
        o.w = h2_u32(__float22half2_rn(make_float2(v1.z, v1.w)));
        g_feat16[i] = o;
    }
    float4 z = make_float4(0.f, 0.f, 0.f, 0.f);
    float4* p = reinterpret_cast<float4*>(g_conv);
    const int n_f4 = N * 8;
    for (int i = tid0; i < n_f4; i += stride) p[i] = z;
    if (tid0 < 2 * C) g_stats[tid0] = 0.f;
}

// Per-warp smem region (5120 B): fp16 A[32][80B] in first 2560 B;
// after the MMAs the same region is reused as float stage[32][40].
// Two-stage pipeline: tile t+1's indices + gather LDGs issue while tile t
// does ldmatrix/MMA/stage/scatter.
__global__ __launch_bounds__(256, 2) void conv_mma_kernel(
    const float* __restrict__ weight,
    const int* __restrict__ pairs_in,
    const int* __restrict__ pairs_out,
    int P)
{
    __shared__ float Ws[C * C];
    __shared__ uint32_t Bs[2][32][18];   // [h0/h1][lane][2f+half], padded stride
    __shared__ __align__(1024) unsigned char Asm[8][5120];

    const int k = blockIdx.y;
    for (int i = threadIdx.x; i < C * C; i += blockDim.x)
        Ws[i] = weight[(size_t)k * (C * C) + i];
    __syncthreads();

    const int wid  = threadIdx.x >> 5;
    const int lane = threadIdx.x & 31;
    const int sub   = lane >> 3;   // scatter: row-within-group 0..3
    const int chunk = lane & 7;    // scatter: 16B chunk 0..7 (fp32 rows)
    const int sub8   = lane >> 2;  // gather: row-within-group 0..7
    const int chunk4 = lane & 3;   // gather: 16B chunk 0..3 (fp16 rows)

    // ---- B fragments: exact 2-way fp16 split of W[k] -> block-shared smem ----
    if (threadIdx.x < 32) {
        const int kq = (lane & 3) * 2, n = lane >> 2;
        #pragma unroll
        for (int kt = 0; kt < 2; kt++) {
            #pragma unroll
            for (int nt = 0; nt < 4; nt++) {
                const int f = kt * 4 + nt;
                const int k0 = kt * 16 + kq, nn = nt * 8 + n;
                const float w0 = Ws[k0 * C + nn];
                const float w1 = Ws[(k0 + 1) * C + nn];
                const float w2 = Ws[(k0 + 8) * C + nn];
                const float w3 = Ws[(k0 + 9) * C + nn];
                const __half a0 = __float2half_rn(w0);
                const __half a1 = __float2half_rn(w1);
                const __half a2 = __float2half_rn(w2);
                const __half a3 = __float2half_rn(w3);
                Bs[0][lane][2 * f]     = h2_u32(__halves2half2(a0, a1));
                Bs[0][lane][2 * f + 1] = h2_u32(__halves2half2(a2, a3));
                Bs[1][lane][2 * f]     = h2_u32(__halves2half2(
                    __float2half_rn(w0 - __half2float(a0)),
                    __float2half_rn(w1 - __half2float(a1))));
                Bs[1][lane][2 * f + 1] = h2_u32(__halves2half2(
                    __float2half_rn(w2 - __half2float(a2)),
                    __float2half_rn(w3 - __half2float(a3))));
            }
        }
    }
    __syncthreads();

    unsigned char* Ab = &Asm[wid][0];
    const uint32_t Aw = smem_u32(Ab);
    float* stg = reinterpret_cast<float*>(Ab);

    const int* __restrict__ pin  = pairs_in  + (size_t)k * P;
    const int* __restrict__ pout = pairs_out + (size_t)k * P;
    const int warp_global = blockIdx.x * 8 + wid;
    const int nwarps = gridDim.x * 8;
    const int step = nwarps * 32;

    int base = warp_global * 32;
    if (base < P) {
        // ---- prologue: indices + gather LDGs for first tile ----
        int p = base + lane;
        int pc = p < P ? p : P - 1;
        int pi = pin[pc];
        int po = pout[pc];
        uint4 rows[4];
        #pragma unroll
        for (int it = 0; it < 4; it++) {
            const int slot = it * 8 + sub8;
            const int row = __shfl_sync(0xffffffffu, pi, slot);
            rows[it] = g_feat16[(size_t)row * 4 + chunk4];
        }

        while (base < P) {
            const int nbase = base + step;

            // ---- commit current tile's rows to smem A ----
            #pragma unroll
            for (int it = 0; it < 4; it++)
                *(uint4*)(Ab + (it * 8 + sub8) * 80 + chunk4 * 16) = rows[it];
            __syncwarp();

            // ---- prefetch next tile (indices + rows) — warp-uniform guard ----
            int npi = 0, npo = 0;
            uint4 nrows[4];
            if (nbase < P) {
                const int np = nbase + lane;
                const int npc = np < P ? np : P - 1;
                npi = pin[npc];
                npo = pout[npc];
                #pragma unroll
                for (int it = 0; it < 4; it++) {
                    const int slot = it * 8 + sub8;
                    const int row = __shfl_sync(0xffffffffu, npi, slot);
                    nrows[it] = g_feat16[(size_t)row * 4 + chunk4];
                }
            }

            // ---- tensor-core compute: 32 HMMA (2 products x 2 m x 4 n x 2 k) ----
            float D[2][4][4] = {};
            const int r  = lane & 15;
            const int cb = (lane >> 4) * 16;
            #pragma unroll
            for (int mt = 0; mt < 2; mt++) {
                uint32_t A[2][4];
                #pragma unroll
                for (int kt = 0; kt < 2; kt++)
                    ldm4(A[kt], Aw + (mt * 16 + r) * 80 + cb + kt * 32);
                #pragma unroll
                for (int nt = 0; nt < 4; nt++) {
                    #pragma unroll
                    for (int kt = 0; kt < 2; kt++) {
                        const int f = kt * 4 + nt;
                        const uint2 b0 = *(const uint2*)&Bs[0][lane][2 * f];
                        const uint2 b1 = *(const uint2*)&Bs[1][lane][2 * f];
                        mma_f16(D[mt][nt], A[kt], b0.x, b0.y);
                        mma_f16(D[mt][nt], A[kt], b1.x, b1.y);
                    }
                }
            }
            __syncwarp();   // all lanes done reading A tile

            // ---- stage D fragments (stride-40 f32 rows, overlays A) ----
            {
                const int drow = lane >> 2, dcol = (lane & 3) * 2;
                #pragma unroll
                for (int mt = 0; mt < 2; mt++) {
                    #pragma unroll
                    for (int nt = 0; nt < 4; nt++) {
                        *(float2*)&stg[(mt * 16 + drow) * 40 + nt * 8 + dcol] =
                            make_float2(D[mt][nt][0], D[mt][nt][1]);
                        *(float2*)&stg[(mt * 16 + drow + 8) * 40 + nt * 8 + dcol] =
                            make_float2(D[mt][nt][2], D[mt][nt][3]);
                    }
                }
            }
            __syncwarp();

            // ---- cooperative coalesced scatter ----
            #pragma unroll
            for (int it = 0; it < 8; it++) {
                const int slot = it * 4 + sub;
                const int row = __shfl_sync(0xffffffffu, po, slot);
                if (base + slot < P) {
                    const float4 v = *(const float4*)&stg[slot * 40 + chunk * 4];
                    asm volatile("red.global.add.v4.f32 [%0], {%1, %2, %3, %4};"
                                 :: "l"(g_conv + (size_t)row * C + chunk * 4),
                                    "f"(v.x), "f"(v.y), "f"(v.z), "f"(v.w)
                                 : "memory");
                }
            }
            __syncwarp();   // scatter reads of stage done before next commit

            // ---- rotate pipeline ----
            base = nbase;
            pi = npi;
            po = npo;
            #pragma unroll
            for (int it = 0; it < 4; it++) rows[it] = nrows[it];
        }
    }
}

__global__ void stats_kernel(int N) {
    __shared__ float4 ssum[256];
    __shared__ float4 sqsum[256];
    const int cg = threadIdx.x & 7;
    const int rr = threadIdx.x >> 3;
    float4 s = make_float4(0.f, 0.f, 0.f, 0.f);
    float4 q = make_float4(0.f, 0.f, 0.f, 0.f);
    for (int row = blockIdx.x * 32 + rr; row < N; row += gridDim.x * 32) {
        const float4 v = *(const float4*)(g_conv + (size_t)row * C + cg * 4);
        const float a0 = v.x >= 0.f ? v.x : LRELU * v.x;
        const float a1 = v.y >= 0.f ? v.y : LRELU * v.y;
        const float a2 = v.z >= 0.f ? v.z : LRELU * v.z;
        const float a3 = v.w >= 0.f ? v.w : LRELU * v.w;
        s.x += a0; s.y += a1; s.z += a2; s.w += a3;
        q.x += a0 * a0; q.y += a1 * a1; q.z += a2 * a2; q.w += a3 * a3;
    }
    ssum[threadIdx.x] = s;
    sqsum[threadIdx.x] = q;
    __syncthreads();
    for (int st = 128; st >= 8; st >>= 1) {
        if (threadIdx.x < st) {
            float4 o = ssum[threadIdx.x + st];
            float4 oq = sqsum[threadIdx.x + st];
            float4 a = ssum[threadIdx.x];
            float4 aq = sqsum[threadIdx.x];
            a.x += o.x; a.y += o.y; a.z += o.z; a.w += o.w;
            aq.x += oq.x; aq.y += oq.y; aq.z += oq.z; aq.w += oq.w;
            ssum[threadIdx.x] = a;
            sqsum[threadIdx.x] = aq;
        }
        __syncthreads();
    }
    if (threadIdx.x < 8) {
        const float4 a = ssum[threadIdx.x];
        const float4 aq = sqsum[threadIdx.x];
        atomicAdd(&g_stats[threadIdx.x * 4 + 0], a.x);
        atomicAdd(&g_stats[threadIdx.x * 4 + 1], a.y);
        atomicAdd(&g_stats[threadIdx.x * 4 + 2], a.z);
        atomicAdd(&g_stats[threadIdx.x * 4 + 3], a.w);
        atomicAdd(&g_stats[C + threadIdx.x * 4 + 0], aq.x);
        atomicAdd(&g_stats[C + threadIdx.x * 4 + 1], aq.y);
        atomicAdd(&g_stats[C + threadIdx.x * 4 + 2], aq.z);
        atomicAdd(&g_stats[C + threadIdx.x * 4 + 3], aq.w);
    }
}

__global__ void final_kernel(const float* __restrict__ gamma,
                             const float* __restrict__ beta,
                             float* __restrict__ out, int N) {
    const int idx0 = blockIdx.x * blockDim.x + threadIdx.x;
    const int stride = gridDim.x * blockDim.x;   // multiple of 8 -> cg invariant
    const int cg = idx0 & 7;
    const float invN = 1.f / (float)N;
    float sc[4], sh[4];
    #pragma unroll
    for (int j = 0; j < 4; j++) {
        const int c = cg * 4 + j;
        const float mean = g_stats[c] * invN;
        const float var  = g_stats[C + c] * invN - mean * mean;
        sc[j] = rsqrtf(var + BN_EPS) * gamma[c];
        sh[j] = beta[c] - mean * sc[j];
    }
    const float4* __restrict__ cp = reinterpret_cast<const float4*>(g_conv);
    float4* __restrict__ op = reinterpret_cast<float4*>(out);
    const int total4 = N * 8;
    for (int idx = idx0; idx < total4; idx += stride) {
        const float4 v = cp[idx];
        float4 y;
        y.x = (v.x >= 0.f ? v.x : LRELU * v.x) * sc[0] + sh[0];
        y.y = (v.y >= 0.f ? v.y : LRELU * v.y) * sc[1] + sh[1];
        y.z = (v.z >= 0.f ? v.z : LRELU * v.z) * sc[2] + sh[2];
        y.w = (v.w >= 0.f ? v.w : LRELU * v.w) * sc[3] + sh[3];
        op[idx] = y;
    }
}

extern "C" void kernel_launch(void* const* d_in, const int* in_sizes, int n_in,
                              void* d_out, int out_size) {
    const float* features = (const float*)d_in[0];
    const float* weight   = (const float*)d_in[1];
    const float* gamma    = (const float*)d_in[2];
    const float* beta     = (const float*)d_in[3];
    const int*   pairs_in = (const int*)d_in[4];
    const int*   pairs_out= (const int*)d_in[5];
    float* out = (float*)d_out;

    const int N = in_sizes[0] / C;
    const int K = in_sizes[1] / (C * C);
    const int P = in_sizes[4] / K;

    prep_kernel<<<2048, 256>>>(features, N);

    dim3 cgrid(64, K);
    conv_mma_kernel<<<cgrid, 256>>>(weight, pairs_in, pairs_out, P);

    stats_kernel<<<1024, 256>>>(N);

    final_kernel<<<2048, 256>>>(gamma, beta, out, N);
}

// round 17
// speedup vs baseline: 1.2685x; 1.0513x over previous
#include <cuda_runtime.h>
#include <cuda_fp16.h>
#include <cstdint>

#define C 32
#define NMAX 500000
#define LRELU 0.01f
#define BN_EPS 1e-5f

// Scratch (static device globals — allocation rules forbid cudaMalloc)
__device__ float g_conv[NMAX * C];        // 64 MB conv accumulator
__device__ uint4 g_feat16[NMAX * 4];      // 32 MB: features as fp16, 64B per row
__device__ float g_stats[2 * C];          // [0:32) sum(act), [32:64) sum(act^2)

__device__ __forceinline__ uint32_t smem_u32(const void* p) {
    uint32_t a;
    asm("{ .reg .u64 t; cvta.to.shared.u64 t, %1; cvt.u32.u64 %0, t; }"
        : "=r"(a) : "l"(p));
    return a;
}
__device__ __forceinline__ void ldm4(uint32_t a[4], uint32_t addr) {
    asm volatile("ldmatrix.sync.aligned.m8n8.x4.shared.b16 {%0,%1,%2,%3}, [%4];"
                 : "=r"(a[0]), "=r"(a[1]), "=r"(a[2]), "=r"(a[3]) : "r"(addr));
}
__device__ __forceinline__ void mma_f16(float d[4], const uint32_t a[4],
                                        uint32_t b0, uint32_t b1) {
    asm volatile("mma.sync.aligned.m16n8k16.row.col.f32.f16.f16.f32 "
                 "{%0,%1,%2,%3}, {%4,%5,%6,%7}, {%8,%9}, {%0,%1,%2,%3};"
                 : "+f"(d[0]), "+f"(d[1]), "+f"(d[2]), "+f"(d[3])
                 : "r"(a[0]), "r"(a[1]), "r"(a[2]), "r"(a[3]),
                   "r"(b0), "r"(b1));
}
__device__ __forceinline__ uint32_t h2_u32(__half2 v) {
    return *reinterpret_cast<uint32_t*>(&v);
}
__device__ __forceinline__ void cp16(uint32_t smem_dst, const void* gmem_src) {
    asm volatile("cp.async.cg.shared.global [%0], [%1], 16;"
                 :: "r"(smem_dst), "l"(gmem_src));
}
__device__ __forceinline__ void cp_commit() {
    asm volatile("cp.async.commit_group;" ::: "memory");
}
__device__ __forceinline__ void cp_wait1() {
    asm volatile("cp.async.wait_group 1;" ::: "memory");
}

// Fused: fp16 pack of features into g_feat16 + zero g_conv + zero g_stats
__global__ void prep_kernel(const float* __restrict__ features, int N) {
    const int stride = gridDim.x * blockDim.x;
    const int tid0 = blockIdx.x * blockDim.x + threadIdx.x;
    const int total_q = N * 4;       // one 16B fp16 chunk (8 channels) per i
    for (int i = tid0; i < total_q; i += stride) {
        const float4 v0 = *((const float4*)features + (size_t)i * 2);
        const float4 v1 = *((const float4*)features + (size_t)i * 2 + 1);
        uint4 o;
        o.x = h2_u32(__float22half2_rn(make_float2(v0.x, v0.y)));
        o.y = h2_u32(__float22half2_rn(make_float2(v0.z, v0.w)));
        o.z = h2_u32(__float22half2_rn(make_float2(v1.x, v1.y)));
        o.w = h2_u32(__float22half2_rn(make_float2(v1.z, v1.w)));
        g_feat16[i] = o;
    }
    float4 z = make_float4(0.f, 0.f, 0.f, 0.f);
    float4* p = reinterpret_cast<float4*>(g_conv);
    const int n_f4 = N * 8;
    for (int i = tid0; i < n_f4; i += stride) p[i] = z;
    if (tid0 < 2 * C) g_stats[tid0] = 0.f;
}

// Per-warp: double-buffered fp16 A tiles (2 x 2560 B, rows at 80 B stride)
// filled by cp.async; separate float stage[32][40] for the scatter transpose.
__global__ __launch_bounds__(256, 2) void conv_mma_kernel(
    const float* __restrict__ weight,
    const int* __restrict__ pairs_in,
    const int* __restrict__ pairs_out,
    int P)
{
    __shared__ float Ws[C * C];
    __shared__ uint32_t Bs[2][32][18];   // [h0/h1][lane][2f+half], padded stride
    __shared__ __align__(1024) unsigned char Abuf[8][2][2560];
    __shared__ __align__(16) float Stg[8][32][40];

    const int k = blockIdx.y;
    for (int i = threadIdx.x; i < C * C; i += blockDim.x)
        Ws[i] = weight[(size_t)k * (C * C) + i];
    __syncthreads();

    const int wid  = threadIdx.x >> 5;
    const int lane = threadIdx.x & 31;
    const int sub   = lane >> 3;   // scatter: row-within-group 0..3
    const int chunk = lane & 7;    // scatter: 16B chunk 0..7 (fp32 rows)
    const int sub8   = lane >> 2;  // gather: row-within-group 0..7
    const int chunk4 = lane & 3;   // gather: 16B chunk 0..3 (fp16 rows)

    // ---- B fragments: exact 2-way fp16 split of W[k] -> block-shared smem ----
    if (threadIdx.x < 32) {
        const int kq = (lane & 3) * 2, n = lane >> 2;
        #pragma unroll
        for (int kt = 0; kt < 2; kt++) {
            #pragma unroll
            for (int nt = 0; nt < 4; nt++) {
                const int f = kt * 4 + nt;
                const int k0 = kt * 16 + kq, nn = nt * 8 + n;
                const float w0 = Ws[k0 * C + nn];
                const float w1 = Ws[(k0 + 1) * C + nn];
                const float w2 = Ws[(k0 + 8) * C + nn];
                const float w3 = Ws[(k0 + 9) * C + nn];
                const __half a0 = __float2half_rn(w0);
                const __half a1 = __float2half_rn(w1);
                const __half a2 = __float2half_rn(w2);
                const __half a3 = __float2half_rn(w3);
                Bs[0][lane][2 * f]     = h2_u32(__halves2half2(a0, a1));
                Bs[0][lane][2 * f + 1] = h2_u32(__halves2half2(a2, a3));
                Bs[1][lane][2 * f]     = h2_u32(__halves2half2(
                    __float2half_rn(w0 - __half2float(a0)),
                    __float2half_rn(w1 - __half2float(a1))));
                Bs[1][lane][2 * f + 1] = h2_u32(__halves2half2(
                    __float2half_rn(w2 - __half2float(a2)),
                    __float2half_rn(w3 - __half2float(a3))));
            }
        }
    }
    __syncthreads();

    const uint32_t Aw0 = smem_u32(&Abuf[wid][0][0]);
    float* stg = &Stg[wid][0][0];

    const int* __restrict__ pin  = pairs_in  + (size_t)k * P;
    const int* __restrict__ pout = pairs_out + (size_t)k * P;
    const int warp_global = blockIdx.x * 8 + wid;
    const int nwarps = gridDim.x * 8;
    const int step = nwarps * 32;

    int base = warp_global * 32;
    if (base < P) {
        // ---- prologue: indices + async gather for first tile into buf 0 ----
        int p = base + lane;
        int pc = p < P ? p : P - 1;
        int pi = pin[pc];
        int po = pout[pc];
        #pragma unroll
        for (int it = 0; it < 4; it++) {
            const int slot = it * 8 + sub8;
            const int row = __shfl_sync(0xffffffffu, pi, slot);
            cp16(Aw0 + slot * 80 + chunk4 * 16,
                 g_feat16 + (size_t)row * 4 + chunk4);
        }
        cp_commit();

        int cur = 0;
        while (base < P) {
            const int nbase = base + step;

            // ---- async gather for next tile into the other buffer ----
            int npo = 0;
            if (nbase < P) {
                const int np = nbase + lane;
                const int npc = np < P ? np : P - 1;
                const int npi = pin[npc];
                npo = pout[npc];
                const uint32_t Awn = Aw0 + (cur ^ 1) * 2560;
                #pragma unroll
                for (int it = 0; it < 4; it++) {
                    const int slot = it * 8 + sub8;
                    const int row = __shfl_sync(0xffffffffu, npi, slot);
                    cp16(Awn + slot * 80 + chunk4 * 16,
                         g_feat16 + (size_t)row * 4 + chunk4);
                }
            }
            cp_commit();          // (possibly empty) group keeps the count in sync
            cp_wait1();           // current tile's copies complete
            __syncwarp();

            // ---- tensor-core compute: 32 HMMA (2 products x 2 m x 4 n x 2 k) ----
            const uint32_t Aw = Aw0 + cur * 2560;
            float D[2][4][4] = {};
            const int r  = lane & 15;
            const int cb = (lane >> 4) * 16;
            #pragma unroll
            for (int mt = 0; mt < 2; mt++) {
                uint32_t A[2][4];
                #pragma unroll
                for (int kt = 0; kt < 2; kt++)
                    ldm4(A[kt], Aw + (mt * 16 + r) * 80 + cb + kt * 32);
                #pragma unroll
                for (int nt = 0; nt < 4; nt++) {
                    #pragma unroll
                    for (int kt = 0; kt < 2; kt++) {
                        const int f = kt * 4 + nt;
                        const uint2 b0 = *(const uint2*)&Bs[0][lane][2 * f];
                        const uint2 b1 = *(const uint2*)&Bs[1][lane][2 * f];
                        mma_f16(D[mt][nt], A[kt], b0.x, b0.y);
                        mma_f16(D[mt][nt], A[kt], b1.x, b1.y);
                    }
                }
            }

            // ---- stage D fragments (stride-40 f32 rows) ----
            {
                const int drow = lane >> 2, dcol = (lane & 3) * 2;
                #pragma unroll
                for (int mt = 0; mt < 2; mt++) {
                    #pragma unroll
                    for (int nt = 0; nt < 4; nt++) {
                        *(float2*)&stg[(mt * 16 + drow) * 40 + nt * 8 + dcol] =
                            make_float2(D[mt][nt][0], D[mt][nt][1]);
                        *(float2*)&stg[(mt * 16 + drow + 8) * 40 + nt * 8 + dcol] =
                            make_float2(D[mt][nt][2], D[mt][nt][3]);
                    }
                }
            }
            __syncwarp();

            // ---- cooperative coalesced scatter ----
            #pragma unroll
            for (int it = 0; it < 8; it++) {
                const int slot = it * 4 + sub;
                const int row = __shfl_sync(0xffffffffu, po, slot);
                if (base + slot < P) {
                    const float4 v = *(const float4*)&stg[slot * 40 + chunk * 4];
                    asm volatile("red.global.add.v4.f32 [%0], {%1, %2, %3, %4};"
                                 :: "l"(g_conv + (size_t)row * C + chunk * 4),
                                    "f"(v.x), "f"(v.y), "f"(v.z), "f"(v.w)
                                 : "memory");
                }
            }
            __syncwarp();   // stage reads done before next iteration overwrites

            // ---- rotate ----
            base = nbase;
            po = npo;
            cur ^= 1;
        }
    }
}

__global__ void stats_kernel(int N) {
    __shared__ float4 ssum[256];
    __shared__ float4 sqsum[256];
    const int cg = threadIdx.x & 7;
    const int rr = threadIdx.x >> 3;
    float4 s = make_float4(0.f, 0.f, 0.f, 0.f);
    float4 q = make_float4(0.f, 0.f, 0.f, 0.f);
    for (int row = blockIdx.x * 32 + rr; row < N; row += gridDim.x * 32) {
        const float4 v = *(const float4*)(g_conv + (size_t)row * C + cg * 4);
        const float a0 = v.x >= 0.f ? v.x : LRELU * v.x;
        const float a1 = v.y >= 0.f ? v.y : LRELU * v.y;
        const float a2 = v.z >= 0.f ? v.z : LRELU * v.z;
        const float a3 = v.w >= 0.f ? v.w : LRELU * v.w;
        s.x += a0; s.y += a1; s.z += a2; s.w += a3;
        q.x += a0 * a0; q.y += a1 * a1; q.z += a2 * a2; q.w += a3 * a3;
    }
    ssum[threadIdx.x] = s;
    sqsum[threadIdx.x] = q;
    __syncthreads();
    for (int st = 128; st >= 8; st >>= 1) {
        if (threadIdx.x < st) {
            float4 o = ssum[threadIdx.x + st];
            float4 oq = sqsum[threadIdx.x + st];
            float4 a = ssum[threadIdx.x];
            float4 aq = sqsum[threadIdx.x];
            a.x += o.x; a.y += o.y; a.z += o.z; a.w += o.w;
            aq.x += oq.x; aq.y += oq.y; aq.z += oq.z; aq.w += oq.w;
            ssum[threadIdx.x] = a;
            sqsum[threadIdx.x] = aq;
        }
        __syncthreads();
    }
    if (threadIdx.x < 8) {
        const float4 a = ssum[threadIdx.x];
        const float4 aq = sqsum[threadIdx.x];
        atomicAdd(&g_stats[threadIdx.x * 4 + 0], a.x);
        atomicAdd(&g_stats[threadIdx.x * 4 + 1], a.y);
        atomicAdd(&g_stats[threadIdx.x * 4 + 2], a.z);
        atomicAdd(&g_stats[threadIdx.x * 4 + 3], a.w);
        atomicAdd(&g_stats[C + threadIdx.x * 4 + 0], aq.x);
        atomicAdd(&g_stats[C + threadIdx.x * 4 + 1], aq.y);
        atomicAdd(&g_stats[C + threadIdx.x * 4 + 2], aq.z);
        atomicAdd(&g_stats[C + threadIdx.x * 4 + 3], aq.w);
    }
}

__global__ void final_kernel(const float* __restrict__ gamma,
                             const float* __restrict__ beta,
                             float* __restrict__ out, int N) {
    const int idx0 = blockIdx.x * blockDim.x + threadIdx.x;
    const int stride = gridDim.x * blockDim.x;   // multiple of 8 -> cg invariant
    const int cg = idx0 & 7;
    const float invN = 1.f / (float)N;
    float sc[4], sh[4];
    #pragma unroll
    for (int j = 0; j < 4; j++) {
        const int c = cg * 4 + j;
        const float mean = g_stats[c] * invN;
        const float var  = g_stats[C + c] * invN - mean * mean;
        sc[j] = rsqrtf(var + BN_EPS) * gamma[c];
        sh[j] = beta[c] - mean * sc[j];
    }
    const float4* __restrict__ cp = reinterpret_cast<const float4*>(g_conv);
    float4* __restrict__ op = reinterpret_cast<float4*>(out);
    const int total4 = N * 8;
    for (int idx = idx0; idx < total4; idx += stride) {
        const float4 v = cp[idx];
        float4 y;
        y.x = (v.x >= 0.f ? v.x : LRELU * v.x) * sc[0] + sh[0];
        y.y = (v.y >= 0.f ? v.y : LRELU * v.y) * sc[1] + sh[1];
        y.z = (v.z >= 0.f ? v.z : LRELU * v.z) * sc[2] + sh[2];
        y.w = (v.w >= 0.f ? v.w : LRELU * v.w) * sc[3] + sh[3];
        op[idx] = y;
    }
}

extern "C" void kernel_launch(void* const* d_in, const int* in_sizes, int n_in,
                              void* d_out, int out_size) {
    const float* features = (const float*)d_in[0];
    const float* weight   = (const float*)d_in[1];
    const float* gamma    = (const float*)d_in[2];
    const float* beta     = (const float*)d_in[3];
    const int*   pairs_in = (const int*)d_in[4];
    const int*   pairs_out= (const int*)d_in[5];
    float* out = (float*)d_out;

    const int N = in_sizes[0] / C;
    const int K = in_sizes[1] / (C * C);
    const int P = in_sizes[4] / K;

    prep_kernel<<<2048, 256>>>(features, N);

    dim3 cgrid(64, K);
    conv_mma_kernel<<<cgrid, 256>>>(weight, pairs_in, pairs_out, P);

    stats_kernel<<<1024, 256>>>(N);

    final_kernel<<<2048, 256>>>(gamma, beta, out, N);
}